// round 1
// baseline (speedup 1.0000x reference)
#include <cuda_runtime.h>

// Problem constants (fixed by the reference)
#define NITEMS 512
#define MAXM   256
#define DIM    128
#define PT     16            // pairs per CTA tile
#define ROWS_PER_ITEM 512    // 2*M rows of scratch per item (need 2M-1)

// Tree scratch buffer: 512 items * 512 rows * 128 floats = 128 MB (device global, allowed)
__device__ float g_buf[(long)NITEMS * ROWS_PER_ITEM * DIM];

// limits may arrive as int32 or int64 (little-endian). limits[0]==0 and
// limits[1]>=1 always, so (as int32) lim[1]==0  <=>  it's int64.
__device__ __forceinline__ int get_limit(const int* lim, bool is64, int i) {
    return is64 ? lim[2 * i] : lim[i];
}

// ---------------------------------------------------------------------------
// Scatter: copy each ragged item into the base of its tree buffer.
// grid = (2, NITEMS), 256 threads. blockIdx.x selects 128-row chunk.
// ---------------------------------------------------------------------------
__global__ void k_scatter(const float* __restrict__ args, const int* __restrict__ lim) {
    int item = blockIdx.y;
    bool is64 = (lim[1] == 0);
    int start = get_limit(lim, is64, item);
    int L     = get_limit(lim, is64, item + 1) - start;
    int row0  = blockIdx.x * 128;
    int nrows = min(128, L - row0);
    if (nrows <= 0) return;
    const float4* src = (const float4*)(args + (long)(start + row0) * DIM);
    float4* dst = (float4*)(g_buf + ((long)item * ROWS_PER_ITEM + row0) * DIM);
    int total = nrows * (DIM / 4);
    for (int f = threadIdx.x; f < total; f += blockDim.x) dst[f] = src[f];
}

// ---------------------------------------------------------------------------
// One tree level for one tile of up to PT pairs of one item.
// X tile [PT,256] -> H=relu(X@W1+b1) [PT,256] -> Y=H@W2+b2 [PT,128] -> LN -> buf
// 256 threads: (ty = tid>>6 in [0,4)) x (tx = tid&63 in [0,64))
// GEMM1 thread tile: 4 rows x 4 cols (cols 4*tx..4*tx+3), W1 streamed as float4.
// GEMM2 thread tile: 4 rows x 2 cols.
// ---------------------------------------------------------------------------
__global__ void __launch_bounds__(256) k_level(
    const float* __restrict__ W1, const float* __restrict__ b1,
    const float* __restrict__ W2, const float* __restrict__ b2,
    const float* __restrict__ lnw, const float* __restrict__ lnb,
    const int* __restrict__ lim, int level)
{
    __shared__ float Xs[PT * 256];   // also reused for Y [PT,128] before LN
    __shared__ float Hs[PT * 256];

    int item = blockIdx.y;
    bool is64 = (lim[1] == 0);
    int L = get_limit(lim, is64, item + 1) - get_limit(lim, is64, item);

    // replay segment (s, l) up to this level
    int s = 0, l = L;
    for (int t = 0; t < level; t++) { int pr = l >> 1; s += 2 * pr; l = (l + 1) >> 1; }
    int pairs = l >> 1;
    int p0 = blockIdx.x * PT;
    if (p0 >= pairs) return;
    int np = min(PT, pairs - p0);

    float* ibuf = g_buf + (long)item * ROWS_PER_ITEM * DIM;
    int tid = threadIdx.x;

    // Load X tile: pairs are contiguous rows -> one contiguous block of np*256 floats
    {
        const float4* src = (const float4*)(ibuf + (long)(s + 2 * p0) * DIM);
        float4* dst = (float4*)Xs;
        int nv = np * 64;                 // np*256/4
        for (int f = tid; f < nv; f += 256) dst[f] = src[f];
        float4 z = make_float4(0.f, 0.f, 0.f, 0.f);
        for (int f = nv + tid; f < PT * 64; f += 256) dst[f] = z;
    }
    __syncthreads();

    int tx = tid & 63, ty = tid >> 6;

    // ---- GEMM1: H = relu(X @ W1 + b1) ----
    {
        float acc[4][4];
        float4 bv = ((const float4*)b1)[tx];
        #pragma unroll
        for (int r = 0; r < 4; r++) {
            acc[r][0] = bv.x; acc[r][1] = bv.y; acc[r][2] = bv.z; acc[r][3] = bv.w;
        }
        const float4* Wv = ((const float4*)W1) + tx;   // row i at Wv[i*64]
        #pragma unroll 4
        for (int i = 0; i < 256; i++) {
            float4 w = Wv[(long)i * 64];
            #pragma unroll
            for (int r = 0; r < 4; r++) {
                float x = Xs[(ty * 4 + r) * 256 + i];
                acc[r][0] += x * w.x; acc[r][1] += x * w.y;
                acc[r][2] += x * w.z; acc[r][3] += x * w.w;
            }
        }
        #pragma unroll
        for (int r = 0; r < 4; r++) {
            float4 h;
            h.x = fmaxf(acc[r][0], 0.f); h.y = fmaxf(acc[r][1], 0.f);
            h.z = fmaxf(acc[r][2], 0.f); h.w = fmaxf(acc[r][3], 0.f);
            ((float4*)(Hs + (ty * 4 + r) * 256))[tx] = h;
        }
    }
    __syncthreads();

    // ---- GEMM2: Y = H @ W2 + b2  (write into Xs as [PT,128]) ----
    {
        float acc[4][2];
        float2 bv = ((const float2*)b2)[tx];
        #pragma unroll
        for (int r = 0; r < 4; r++) { acc[r][0] = bv.x; acc[r][1] = bv.y; }
        const float2* Wv = ((const float2*)W2) + tx;   // row i at Wv[i*64]
        #pragma unroll 4
        for (int i = 0; i < 256; i++) {
            float2 w = Wv[(long)i * 64];
            #pragma unroll
            for (int r = 0; r < 4; r++) {
                float h = Hs[(ty * 4 + r) * 256 + i];
                acc[r][0] += h * w.x; acc[r][1] += h * w.y;
            }
        }
        #pragma unroll
        for (int r = 0; r < 4; r++)
            ((float2*)(Xs + (ty * 4 + r) * 128))[tx] = make_float2(acc[r][0], acc[r][1]);
    }
    __syncthreads();

    // ---- LayerNorm per row + write back; warp w handles rows 2w, 2w+1 ----
    int warp = tid >> 5, lane = tid & 31;
    #pragma unroll
    for (int rr = 0; rr < 2; rr++) {
        int row = warp * 2 + rr;
        if (row >= np) continue;                  // uniform per warp
        float4 y = ((float4*)(Xs + row * 128))[lane];
        float sum = y.x + y.y + y.z + y.w;
        float sq  = y.x * y.x + y.y * y.y + y.z * y.z + y.w * y.w;
        #pragma unroll
        for (int o = 16; o > 0; o >>= 1) {
            sum += __shfl_xor_sync(0xFFFFFFFFu, sum, o);
            sq  += __shfl_xor_sync(0xFFFFFFFFu, sq, o);
        }
        float mu  = sum * (1.f / 128.f);
        float var = sq * (1.f / 128.f) - mu * mu;
        float rs  = rsqrtf(var + 1e-5f);
        float4 wv = ((const float4*)lnw)[lane];
        float4 bv = ((const float4*)lnb)[lane];
        float4 o;
        o.x = (y.x - mu) * rs * wv.x + bv.x;
        o.y = (y.y - mu) * rs * wv.y + bv.y;
        o.z = (y.z - mu) * rs * wv.z + bv.z;
        o.w = (y.w - mu) * rs * wv.w + bv.w;
        ((float4*)(ibuf + (long)(s + l + p0 + row) * DIM))[lane] = o;
    }
}

// ---------------------------------------------------------------------------
// Gather roots: out[i] = buf_i[2L-2]  (== the input row when L==1)
// ---------------------------------------------------------------------------
__global__ void k_gather(float* __restrict__ out, const int* __restrict__ lim) {
    int item = blockIdx.x;
    bool is64 = (lim[1] == 0);
    int L = get_limit(lim, is64, item + 1) - get_limit(lim, is64, item);
    const float* src = g_buf + ((long)item * ROWS_PER_ITEM + (2 * L - 2)) * DIM;
    out[item * DIM + threadIdx.x] = src[threadIdx.x];
}

// ---------------------------------------------------------------------------
extern "C" void kernel_launch(void* const* d_in, const int* in_sizes, int n_in,
                              void* d_out, int out_size) {
    const float* args = (const float*)d_in[0];
    const int*   lim  = (const int*)d_in[1];
    const float* W1   = (const float*)d_in[2];
    const float* b1   = (const float*)d_in[3];
    const float* W2   = (const float*)d_in[4];
    const float* b2   = (const float*)d_in[5];
    const float* lnw  = (const float*)d_in[6];
    const float* lnb  = (const float*)d_in[7];
    float* out = (float*)d_out;
    (void)in_sizes; (void)n_in; (void)out_size;

    dim3 gsc(2, NITEMS);
    k_scatter<<<gsc, 256>>>(args, lim);

    for (int k = 0; k < 8; k++) {
        int maxpairs = MAXM >> (k + 1);
        if (maxpairs < 1) maxpairs = 1;
        int tiles = (maxpairs + PT - 1) / PT;
        dim3 g(tiles, NITEMS);
        k_level<<<g, 256>>>(W1, b1, W2, b2, lnw, lnb, lim, k);
    }

    k_gather<<<NITEMS, DIM>>>(out, lim);
}

// round 3
// speedup vs baseline: 1.6327x; 1.6327x over previous
#include <cuda_runtime.h>

#define NITEMS 512
#define MAXM   256
#define DIM    128
#define PT     32            // pairs per CTA tile (batched across items)
#define ROWS_PER_ITEM 512
#define MAXPAIRS 131072      // >= 512*255

// Tree scratch buffer: 512 items * 512 rows * 128 floats = 128 MB
__device__ float g_buf[(long)NITEMS * ROWS_PER_ITEM * DIM];
// Batched pair index lists (built per run by k_prep); zero-init at load
__device__ int g_src[MAXPAIRS];   // first source row (pair rows are contiguous)
__device__ int g_dst[MAXPAIRS];   // destination row
__device__ int g_count[8];
__device__ int g_base[8];

typedef unsigned long long ull;

__device__ __forceinline__ ull ffma2(ull a, ull b, ull c) {
    ull d; asm("fma.rn.f32x2 %0, %1, %2, %3;" : "=l"(d) : "l"(a), "l"(b), "l"(c));
    return d;
}
__device__ __forceinline__ ull bcast2(float x) {
    ull d; asm("mov.b64 %0, {%1, %1};" : "=l"(d) : "f"(x)); return d;
}
__device__ __forceinline__ float2 unpack2(ull v) {
    float2 r; asm("mov.b64 {%0, %1}, %2;" : "=f"(r.x), "=f"(r.y) : "l"(v)); return r;
}

__device__ __forceinline__ int get_limit(const int* lim, bool is64, int i) {
    return is64 ? lim[2 * i] : lim[i];
}

// ---------------------------------------------------------------------------
// Scatter: copy each ragged item into the base of its tree buffer.
// ---------------------------------------------------------------------------
__global__ void k_scatter(const float* __restrict__ args, const int* __restrict__ lim) {
    int item = blockIdx.y;
    bool is64 = (lim[1] == 0);
    int start = get_limit(lim, is64, item);
    int L     = get_limit(lim, is64, item + 1) - start;
    int row0  = blockIdx.x * 128;
    int nrows = min(128, L - row0);
    if (nrows <= 0) return;
    const float4* src = (const float4*)(args + (long)(start + row0) * DIM);
    float4* dst = (float4*)(g_buf + ((long)item * ROWS_PER_ITEM + row0) * DIM);
    int total = nrows * (DIM / 4);
    for (int f = threadIdx.x; f < total; f += blockDim.x) dst[f] = src[f];
}

// ---------------------------------------------------------------------------
// Prep: build global (batched-across-items) pair lists per level.
// 1 block, 512 threads (one per item). Hillis-Steele scan in smem.
// ---------------------------------------------------------------------------
__global__ void k_prep(const int* __restrict__ lim) {
    __shared__ int sc[NITEMS];
    int i = threadIdx.x;
    bool is64 = (lim[1] == 0);
    int L = get_limit(lim, is64, i + 1) - get_limit(lim, is64, i);
    int s = 0, l = L, base = 0;
    int rowb = i * ROWS_PER_ITEM;
    for (int k = 0; k < 8; k++) {
        int pr = l >> 1;
        sc[i] = pr;
        __syncthreads();
        for (int off = 1; off < NITEMS; off <<= 1) {
            int v = sc[i];
            int w = (i >= off) ? sc[i - off] : 0;
            __syncthreads();
            sc[i] = v + w;
            __syncthreads();
        }
        int excl = sc[i] - pr;
        int tot  = sc[NITEMS - 1];
        if (i == 0) { g_count[k] = tot; g_base[k] = base; }
        int e = base + excl;
        for (int p = 0; p < pr; p++) {
            g_src[e + p] = rowb + s + 2 * p;
            g_dst[e + p] = rowb + s + l + p;
        }
        s += 2 * pr;
        l = (l + 1) >> 1;
        base += tot;
        __syncthreads();   // protect sc before next level's store
    }
}

// ---------------------------------------------------------------------------
// Batched level kernel: CTA = up to PT(=32) pairs gathered from g_src/g_dst.
// X [32,256] -> H = relu(X@W1+b1) [32,256] -> Y = H@W2+b2 [32,128] -> LN -> buf
// 256 threads: tx = tid&63, ty = tid>>6. GEMM1 tile 8 rows x 4 cols (f32x2 x2).
// Dynamic smem: Xs 32KB + Hs 32KB = 64KB.
// ---------------------------------------------------------------------------
extern __shared__ float dyn_smem[];

__global__ void __launch_bounds__(256, 2) k_level(
    const float* __restrict__ W1, const float* __restrict__ b1,
    const float* __restrict__ W2, const float* __restrict__ b2,
    const float* __restrict__ lnw, const float* __restrict__ lnb,
    int level)
{
    int cnt  = g_count[level];
    int base = g_base[level];
    int j0 = blockIdx.x * PT;
    if (j0 >= cnt) return;
    int np = min(PT, cnt - j0);

    float* Xs = dyn_smem;            // [PT][256], later reused as Y [PT][128]
    float* Hs = dyn_smem + PT * 256; // [PT][256]

    int tid = threadIdx.x;

    // Gather X: each pair = 2 contiguous buffer rows = 64 float4.
    // Pair index clamped to the first valid pair for padding lanes (g_src is
    // zero-initialized, so any index read here is within g_buf bounds).
    const float4* gb4 = (const float4*)g_buf;
    {
        float4* xd = (float4*)Xs;
        #pragma unroll
        for (int k = 0; k < (PT * 64) / 256; k++) {
            int f = tid + k * 256;
            int q = f >> 6, w = f & 63;
            int rowq = g_src[base + j0 + ((q < np) ? q : 0)];
            xd[f] = gb4[(long)rowq * 32 + w];
        }
    }
    __syncthreads();

    int tx = tid & 63, ty = tid >> 6;   // tx: 64 col-groups, ty: 4 row-groups

    // ---- GEMM1: H = relu(X @ W1 + b1); rows ty*8..+7, cols 4tx..+3 ----
    {
        ull acc[8][2];
        const ulonglong2* b1v = (const ulonglong2*)b1;
        ulonglong2 bb = b1v[tx];
        #pragma unroll
        for (int r = 0; r < 8; r++) { acc[r][0] = bb.x; acc[r][1] = bb.y; }

        const ulonglong2* W1v = (const ulonglong2*)W1;  // row i at W1v[i*64 + tx]
        #pragma unroll 2
        for (int i = 0; i < 256; i += 4) {
            ulonglong2 w0 = W1v[(i + 0) * 64 + tx];
            ulonglong2 w1 = W1v[(i + 1) * 64 + tx];
            ulonglong2 w2 = W1v[(i + 2) * 64 + tx];
            ulonglong2 w3 = W1v[(i + 3) * 64 + tx];
            #pragma unroll
            for (int r = 0; r < 8; r++) {
                float4 x = *(const float4*)&Xs[(ty * 8 + r) * 256 + i];
                ull x0 = bcast2(x.x), x1 = bcast2(x.y), x2 = bcast2(x.z), x3 = bcast2(x.w);
                acc[r][0] = ffma2(x0, w0.x, acc[r][0]); acc[r][1] = ffma2(x0, w0.y, acc[r][1]);
                acc[r][0] = ffma2(x1, w1.x, acc[r][0]); acc[r][1] = ffma2(x1, w1.y, acc[r][1]);
                acc[r][0] = ffma2(x2, w2.x, acc[r][0]); acc[r][1] = ffma2(x2, w2.y, acc[r][1]);
                acc[r][0] = ffma2(x3, w3.x, acc[r][0]); acc[r][1] = ffma2(x3, w3.y, acc[r][1]);
            }
        }
        #pragma unroll
        for (int r = 0; r < 8; r++) {
            float2 a = unpack2(acc[r][0]);
            float2 b = unpack2(acc[r][1]);
            float4 h;
            h.x = fmaxf(a.x, 0.f); h.y = fmaxf(a.y, 0.f);
            h.z = fmaxf(b.x, 0.f); h.w = fmaxf(b.y, 0.f);
            ((float4*)(Hs + (ty * 8 + r) * 256))[tx] = h;
        }
    }
    __syncthreads();

    // ---- GEMM2: Y = H @ W2 + b2; rows ty*8..+7, cols 2tx..+1 (one f32x2 acc) ----
    {
        ull acc[8];
        ull bb = ((const ull*)b2)[tx];
        #pragma unroll
        for (int r = 0; r < 8; r++) acc[r] = bb;

        const ull* W2v = (const ull*)W2;   // row i at W2v[i*64 + tx]
        #pragma unroll 2
        for (int i = 0; i < 256; i += 4) {
            ull w0 = W2v[(i + 0) * 64 + tx];
            ull w1 = W2v[(i + 1) * 64 + tx];
            ull w2 = W2v[(i + 2) * 64 + tx];
            ull w3 = W2v[(i + 3) * 64 + tx];
            #pragma unroll
            for (int r = 0; r < 8; r++) {
                float4 h = *(const float4*)&Hs[(ty * 8 + r) * 256 + i];
                acc[r] = ffma2(bcast2(h.x), w0, acc[r]);
                acc[r] = ffma2(bcast2(h.y), w1, acc[r]);
                acc[r] = ffma2(bcast2(h.z), w2, acc[r]);
                acc[r] = ffma2(bcast2(h.w), w3, acc[r]);
            }
        }
        __syncthreads();   // everyone done reading Xs (GEMM1) before Y overwrites it
        #pragma unroll
        for (int r = 0; r < 8; r++) {
            float2 y = unpack2(acc[r]);
            ((float2*)(Xs + (ty * 8 + r) * 128))[tx] = y;
        }
    }
    __syncthreads();

    // ---- LayerNorm per pair-row + scatter to dst rows. Warp w: rows 4w..4w+3 ----
    {
        int warp = tid >> 5, lane = tid & 31;
        float4* gb4w = (float4*)g_buf;
        #pragma unroll
        for (int rr = 0; rr < 4; rr++) {
            int row = warp * 4 + rr;
            int d = (row < np) ? g_dst[base + j0 + row] : -1;
            float4 y = ((float4*)(Xs + row * 128))[lane];
            float sum = y.x + y.y + y.z + y.w;
            float sq  = y.x * y.x + y.y * y.y + y.z * y.z + y.w * y.w;
            #pragma unroll
            for (int o = 16; o > 0; o >>= 1) {
                sum += __shfl_xor_sync(0xFFFFFFFFu, sum, o);
                sq  += __shfl_xor_sync(0xFFFFFFFFu, sq, o);
            }
            float mu  = sum * (1.f / 128.f);
            float var = sq * (1.f / 128.f) - mu * mu;
            float rs  = rsqrtf(var + 1e-5f);
            float4 wv = ((const float4*)lnw)[lane];
            float4 bv = ((const float4*)lnb)[lane];
            float4 o;
            o.x = (y.x - mu) * rs * wv.x + bv.x;
            o.y = (y.y - mu) * rs * wv.y + bv.y;
            o.z = (y.z - mu) * rs * wv.z + bv.z;
            o.w = (y.w - mu) * rs * wv.w + bv.w;
            if (d >= 0) gb4w[(long)d * 32 + lane] = o;
        }
    }
}

// ---------------------------------------------------------------------------
__global__ void k_gather(float* __restrict__ out, const int* __restrict__ lim) {
    int item = blockIdx.x;
    bool is64 = (lim[1] == 0);
    int L = get_limit(lim, is64, item + 1) - get_limit(lim, is64, item);
    const float* src = g_buf + ((long)item * ROWS_PER_ITEM + (2 * L - 2)) * DIM;
    out[item * DIM + threadIdx.x] = src[threadIdx.x];
}

// ---------------------------------------------------------------------------
extern "C" void kernel_launch(void* const* d_in, const int* in_sizes, int n_in,
                              void* d_out, int out_size) {
    const float* args = (const float*)d_in[0];
    const int*   lim  = (const int*)d_in[1];
    const float* W1   = (const float*)d_in[2];
    const float* b1   = (const float*)d_in[3];
    const float* W2   = (const float*)d_in[4];
    const float* b2   = (const float*)d_in[5];
    const float* lnw  = (const float*)d_in[6];
    const float* lnb  = (const float*)d_in[7];
    float* out = (float*)d_out;
    (void)in_sizes; (void)n_in; (void)out_size;

    // Unconditional (no static guard): not a stream op, capture-safe, deterministic.
    cudaFuncSetAttribute(k_level, cudaFuncAttributeMaxDynamicSharedMemorySize, 65536);

    dim3 gsc(2, NITEMS);
    k_scatter<<<gsc, 256>>>(args, lim);
    k_prep<<<1, NITEMS>>>(lim);

    for (int k = 0; k < 8; k++) {
        int maxpairs = NITEMS * (MAXM >> (k + 1));   // worst case; CTAs early-exit
        int ctas = (maxpairs + PT - 1) / PT;
        k_level<<<ctas, 256, 65536>>>(W1, b1, W2, b2, lnw, lnb, k);
    }

    k_gather<<<NITEMS, DIM>>>(out, lim);
}